// round 1
// baseline (speedup 1.0000x reference)
#include <cuda_runtime.h>
#include <math.h>

#define HH 512
#define WW 512
#define BMAX 16
#define NACC 72   // 45 AtA (upper tri) + 27 Atb

__device__ double g_acc[BMAX * NACC];

__global__ void zero_k() {
    int i = blockIdx.x * blockDim.x + threadIdx.x;
    if (i < BMAX * NACC) g_acc[i] = 0.0;
}

__global__ __launch_bounds__(256) void accum_k(const float* __restrict__ img,
                                               const float* __restrict__ dep,
                                               const float* __restrict__ alb) {
    const int b = blockIdx.y;
    const float* __restrict__ dptr = dep + (size_t)b * HH * WW;
    const float* __restrict__ i0 = img + (size_t)b * 3 * HH * WW;
    const float* __restrict__ i1 = i0 + HH * WW;
    const float* __restrict__ i2 = i1 + HH * WW;
    const float* __restrict__ a2 = alb + (size_t)b * 3 * HH * WW + 2 * HH * WW;

    const float INVF = (float)(1.0 / 608.365);
    const double PI_ = 3.14159;
    const float C0 = (float)(PI_ * sqrt(1.0 / (4.0 * PI_)));
    const float C1 = (float)(2.0 * PI_ / 3.0 * sqrt(3.0 / (4.0 * PI_)));
    const float C2 = (float)(PI_ / 4.0 * 0.5 * sqrt(5.0 / (4.0 * PI_)));
    const float C3 = (float)(PI_ / 4.0 * 3.0 * sqrt(5.0 / (12.0 * PI_)));
    const float C4 = (float)(PI_ / 4.0 * 3.0 * sqrt(5.0 / (48.0 * PI_)));

    float s[NACC];
#pragma unroll
    for (int k = 0; k < NACC; k++) s[k] = 0.f;

    for (int y = 1 + blockIdx.x; y < HH - 1; y += gridDim.x) {
        const float v  = (y - 256.0f) * INVF;
        const float vN = (y - 1 - 256.0f) * INVF;
        const float vS = (y + 1 - 256.0f) * INVF;
        const int row = y * WW;
        for (int x = 1 + threadIdx.x; x < WW - 1; x += blockDim.x) {
            // depth = (depth_target + 1)/2, 5-point stencil
            float dc = (dptr[row + x]      + 1.f) * 0.5f;
            float dE = (dptr[row + x + 1]  + 1.f) * 0.5f;
            float dW = (dptr[row + x - 1]  + 1.f) * 0.5f;
            float dS = (dptr[row + WW + x] + 1.f) * 0.5f;
            float dN = (dptr[row - WW + x] + 1.f) * 0.5f;

            float u  = (x - 256.0f) * INVF;
            float uE = (x + 1 - 256.0f) * INVF;
            float uW = (x - 1 - 256.0f) * INVF;

            // vw = p(y,x) - p(y,x+1)
            float awx = u * dc - uE * dE, awy = v * (dc - dE), awz = dc - dE;
            // vs = p(y+1,x) - p(y,x)
            float asx = u * (dS - dc), asy = vS * dS - v * dc, asz = dS - dc;
            // ve = p(y,x) - p(y,x-1)
            float aex = u * dc - uW * dW, aey = v * (dc - dW), aez = dc - dW;
            // vn = p(y-1,x) - p(y,x)
            float anx = u * (dN - dc), any_ = vN * dN - v * dc, anz = dN - dc;

            // normal = cross(vw, vs) + cross(ve, vn)
            float nx = (awy * asz - awz * asy) + (aey * anz - aez * any_);
            float ny = (awz * asx - awx * asz) + (aez * anx - aex * anz);
            float nz = (awx * asy - awy * asx) + (aex * any_ - aey * anx);

            float mag2 = nx * nx + ny * ny + nz * nz;
            float mag = sqrtf(mag2);
            float inv = 1.0f / mag;

            float Nv[9];
            Nv[0] = C0 * mag;
            Nv[1] = C1 * nz;
            Nv[2] = C1 * nx;
            Nv[3] = C1 * ny;
            Nv[4] = C2 * (2.f * nz * nz - nx * nx - ny * ny) * inv;
            Nv[5] = C3 * nx * nz * inv;
            Nv[6] = C3 * ny * nz * inv;
            Nv[7] = C4 * (nx * nx - ny * ny) * inv;
            Nv[8] = C3 * nx * ny * inv;

            // mask from channel 0 of (input+1)/2
            float m0 = (i0[row + x] + 1.0f) * 0.5f;
            float mask = (m0 != 0.0f) ? 1.0f : 0.0f;
            float rho = a2[row + x] * mask;
            float w = rho * rho;

            float b0 = m0 * mask;
            float b1 = (i1[row + x] + 1.0f) * 0.5f * mask;
            float b2 = (i2[row + x] + 1.0f) * 0.5f * mask;

            float wN[9];
#pragma unroll
            for (int i = 0; i < 9; i++) wN[i] = w * Nv[i];

            int k = 0;
#pragma unroll
            for (int i = 0; i < 9; i++)
#pragma unroll
                for (int j = i; j < 9; j++) { s[k] += wN[i] * Nv[j]; k++; }

            float r0 = b0 * rho, r1 = b1 * rho, r2 = b2 * rho;
#pragma unroll
            for (int i = 0; i < 9; i++) {
                s[45 + i] += r0 * Nv[i];
                s[54 + i] += r1 * Nv[i];
                s[63 + i] += r2 * Nv[i];
            }
        }
    }

    // block reduction: warp shuffle -> smem -> double atomics
    __shared__ float red[8][NACC];
    int lane = threadIdx.x & 31;
    int warp = threadIdx.x >> 5;
#pragma unroll
    for (int k = 0; k < NACC; k++) {
        float vsum = s[k];
#pragma unroll
        for (int off = 16; off > 0; off >>= 1)
            vsum += __shfl_down_sync(0xffffffffu, vsum, off);
        if (lane == 0) red[warp][k] = vsum;
    }
    __syncthreads();
    for (int k = threadIdx.x; k < NACC; k += blockDim.x) {
        double t = 0.0;
#pragma unroll
        for (int wi = 0; wi < 8; wi++) t += (double)red[wi][k];
        atomicAdd(&g_acc[b * NACC + k], t);
    }
}

__global__ void solve_k(float* __restrict__ out, int B) {
    int b = blockIdx.x * blockDim.x + threadIdx.x;
    if (b >= B) return;

    double Aug[9][12];
    {
        int k = 0;
        for (int i = 0; i < 9; i++)
            for (int j = i; j < 9; j++) {
                double a = g_acc[b * NACC + k]; k++;
                Aug[i][j] = a;
                Aug[j][i] = a;
            }
        for (int c = 0; c < 3; c++)
            for (int i = 0; i < 9; i++)
                Aug[i][9 + c] = g_acc[b * NACC + 45 + 9 * c + i];
    }

    // Gaussian elimination with partial pivoting
    for (int col = 0; col < 9; col++) {
        int piv = col;
        double best = fabs(Aug[col][col]);
        for (int r = col + 1; r < 9; r++) {
            double a = fabs(Aug[r][col]);
            if (a > best) { best = a; piv = r; }
        }
        if (piv != col) {
            for (int j = 0; j < 12; j++) {
                double t = Aug[col][j]; Aug[col][j] = Aug[piv][j]; Aug[piv][j] = t;
            }
        }
        double invp = 1.0 / Aug[col][col];
        for (int r = col + 1; r < 9; r++) {
            double f = Aug[r][col] * invp;
            for (int j = col; j < 12; j++) Aug[r][j] -= f * Aug[col][j];
        }
    }

    // back substitution, 3 RHS
    double X[9][3];
    for (int i = 8; i >= 0; i--) {
        double di = 1.0 / Aug[i][i];
        for (int c = 0; c < 3; c++) {
            double t = Aug[i][9 + c];
            for (int j = i + 1; j < 9; j++) t -= Aug[i][j] * X[j][c];
            X[i][c] = t * di;
        }
    }

    for (int c = 0; c < 3; c++)
        for (int i = 0; i < 9; i++)
            out[b * 27 + c * 9 + i] = (float)X[i][c];
}

extern "C" void kernel_launch(void* const* d_in, const int* in_sizes, int n_in,
                              void* d_out, int out_size) {
    const float* img = (const float*)d_in[0];   // input_img (B,3,H,W)
    const float* dep = (const float*)d_in[1];   // depth_target (B,1,H,W)
    const float* alb = (const float*)d_in[2];   // albedo (B,3,H,W)
    int B = in_sizes[1] / (HH * WW);
    if (B > BMAX) B = BMAX;

    zero_k<<<(BMAX * NACC + 255) / 256, 256>>>();
    dim3 grid(37, B);
    accum_k<<<grid, 256>>>(img, dep, alb);
    solve_k<<<1, 32>>>((float*)d_out, B);
}